// round 5
// baseline (speedup 1.0000x reference)
#include <cuda_runtime.h>

// FactorGNN fused pipeline.
// Reference math (dead attention branch removed):
//   A = supports, A[j,j] = (diag==0 ? 1 : diag)
//   deg[j] = sum_i A[i,j];  dinv = deg>0 ? rsqrt(deg) : 0
//   hs[b,i,o] = dinv[i] * (x[b,i,:] @ W_gcn)          (M matrix, cols c=b*16+o)
//   C[j,c]   = sum_i supports[i,j] * hs[i,c]          (big GEMM, split-K=8)
//   g[b,j,o] = relu(dinv[j]*(C + corr[j]*hs[j,c]) + b_gcn[o]), corr=(diag==0)
//   out[b,n,:] = g.reshape(.,160) @ W_out + b_out

#define NF     10240
#define NB     4
#define NN     1024
#define FF     10
#define DD     16
#define DOUTC  16
#define NCOL   64            // NB*DOUTC
#define ROWCH  40            // 10240/256 row chunks for deg pass
#define KSPLIT 8
#define KCHUNK (NF/KSPLIT)   // 1280
#define BM     64
#define BN     64
#define BK     16
#define NTILES (KCHUNK/BK)   // 80

// Scratch (static device globals: allocation-free per harness rules)
__device__ float g_M[NF*NCOL];                 // hs, [i][c]
__device__ float g_C[KSPLIT][NF*NCOL];         // split-K partials
__device__ float g_degpart[ROWCH*NF];
__device__ float g_dinv[NF];
__device__ float g_corr[NF];

// ---- packed f32x2 helpers (sm_103a FFMA2 path) ----
__device__ __forceinline__ unsigned long long pk2(float lo, float hi) {
    unsigned long long r;
    asm("mov.b64 %0, {%1, %2};" : "=l"(r) : "f"(lo), "f"(hi));
    return r;
}
__device__ __forceinline__ void fma2(unsigned long long& d,
                                     unsigned long long a, unsigned long long b) {
    asm("fma.rn.f32x2 %0, %1, %2, %0;" : "+l"(d) : "l"(a), "l"(b));
}
__device__ __forceinline__ float2 upk2(unsigned long long v) {
    float2 f;
    asm("mov.b64 {%0, %1}, %2;" : "=f"(f.x), "=f"(f.y) : "l"(v));
    return f;
}

// K1: partial column sums of supports (deg before diag fix)
__global__ void k_degpart(const float* __restrict__ S) {
    int j  = blockIdx.x * 256 + threadIdx.x;
    int r0 = blockIdx.y * 256;
    const float* p = S + (size_t)r0 * NF + j;
    float s = 0.f;
#pragma unroll 8
    for (int r = 0; r < 256; r++) s += p[(size_t)r * NF];
    g_degpart[blockIdx.y * NF + j] = s;
}

// K2: reduce partials, apply self-loop fix, produce dinv & corr
__global__ void k_finalize(const float* __restrict__ S) {
    int j = blockIdx.x * 256 + threadIdx.x;
    float s = 0.f;
#pragma unroll
    for (int p = 0; p < ROWCH; p++) s += g_degpart[p * NF + j];
    float diag = S[(size_t)j * NF + j];
    float corr = (diag == 0.f) ? 1.f : 0.f;   // A_jj - S_jj
    float deg  = s + corr;                    // colsum already includes diag
    g_dinv[j] = (deg > 0.f) ? rsqrtf(deg) : 0.f;
    g_corr[j] = corr;
}

// K3: hs = dinv[i] * (x @ W_gcn), layout g_M[i*64 + b*16 + o]
__global__ void k_hs(const float* __restrict__ x, const float* __restrict__ Wg) {
    __shared__ float sW[DD * DOUTC];
    if (threadIdx.x < DD * DOUTC) sW[threadIdx.x] = Wg[threadIdx.x];
    __syncthreads();
    int g = blockIdx.x * 256 + threadIdx.x;   // NB*NF*16 threads
    int o = g & 15;
    int rest = g >> 4;
    int i = rest % NF;
    int b = rest / NF;
    const float* xr = x + ((size_t)b * NF + i) * DD;
    float h = 0.f;
#pragma unroll
    for (int d = 0; d < DD; d++) h = fmaf(xr[d], sW[d * DOUTC + o], h);
    g_M[i * NCOL + b * DOUTC + o] = g_dinv[i] * h;
}

// K4: C[ks][j,c] = sum_{i in kchunk} S[i,j] * M[i,c]
// BM=BN=64, BK=16, 256 threads, per-thread 4j x 4c via f32x2 (j-paired accs).
__global__ __launch_bounds__(256) void k_gemm(const float* __restrict__ S) {
    __shared__ float As[2][BK * BM];
    __shared__ float Bs[2][BK * BN];
    const int jt = blockIdx.x, ks = blockIdx.y;
    const int j0 = jt * BM;
    const int k0 = ks * KCHUNK;
    const int tx = threadIdx.x;
    const int trow = tx >> 4, tcol = tx & 15;
    const int lrow = tx >> 4;            // 0..15 (load row)
    const int lcol = (tx & 15) * 4;      // 0..60 (load col, float4)

    const float* Sp = S   + ((size_t)(k0 + lrow)) * NF   + j0 + lcol;
    const float* Mp = g_M + ((size_t)(k0 + lrow)) * NCOL + lcol;

    unsigned long long acc[2][4];        // [j-pair][c], each holds j,j+1
#pragma unroll
    for (int p = 0; p < 2; p++)
#pragma unroll
        for (int c = 0; c < 4; c++) acc[p][c] = 0ull;

    float4 aR = *(const float4*)Sp;
    float4 bR = *(const float4*)Mp;
    *(float4*)&As[0][lrow * BM + lcol] = aR;
    *(float4*)&Bs[0][lrow * BN + lcol] = bR;

    for (int t = 0; t < NTILES; ++t) {
        __syncthreads();
        const int buf = t & 1;
        if (t + 1 < NTILES) {
            aR = *(const float4*)(Sp + (size_t)(t + 1) * BK * NF);
            bR = *(const float4*)(Mp + (size_t)(t + 1) * BK * NCOL);
        }
#pragma unroll
        for (int kk = 0; kk < BK; ++kk) {
            float4 av = *(const float4*)&As[buf][kk * BM + trow * 4];
            float4 bv = *(const float4*)&Bs[buf][kk * BN + tcol * 4];
            unsigned long long a01 = pk2(av.x, av.y);   // free reg-pair alias
            unsigned long long a23 = pk2(av.z, av.w);
            float bc[4] = {bv.x, bv.y, bv.z, bv.w};
#pragma unroll
            for (int c = 0; c < 4; c++) {
                unsigned long long b2 = pk2(bc[c], bc[c]);  // 1 MOV (ALU pipe)
                fma2(acc[0][c], a01, b2);
                fma2(acc[1][c], a23, b2);
            }
        }
        if (t + 1 < NTILES) {
            const int nb = buf ^ 1;
            *(float4*)&As[nb][lrow * BM + lcol] = aR;
            *(float4*)&Bs[nb][lrow * BN + lcol] = bR;
        }
    }

    // write partials: rows j0 + trow*4 + {0..3}, cols tcol*4 + {0..3}
    float* Cp = g_C[ks] + ((size_t)(j0 + trow * 4)) * NCOL + tcol * 4;
#pragma unroll
    for (int p = 0; p < 2; p++) {
        float2 v0 = upk2(acc[p][0]);
        float2 v1 = upk2(acc[p][1]);
        float2 v2 = upk2(acc[p][2]);
        float2 v3 = upk2(acc[p][3]);
        *(float4*)(Cp + (size_t)(p * 2 + 0) * NCOL) = make_float4(v0.x, v1.x, v2.x, v3.x);
        *(float4*)(Cp + (size_t)(p * 2 + 1) * NCOL) = make_float4(v0.y, v1.y, v2.y, v3.y);
    }
}

// K5: epilogue (sum split-K, diag corr, dinv[j], bias, relu) + output GEMM 160x16
__global__ void k_out(const float* __restrict__ Wout, const float* __restrict__ bgcn,
                      const float* __restrict__ bout, float* __restrict__ out) {
    __shared__ float sW[FF * DOUTC * DOUTC];   // 160x16
    __shared__ float sg[8][FF * DOUTC];        // 8 rows x 160
    __shared__ float sbg[DOUTC], sbo[DOUTC];
    const int tx = threadIdx.x;
    for (int i = tx; i < FF * DOUTC * DOUTC; i += 128) sW[i] = Wout[i];
    if (tx < DOUTC) { sbg[tx] = bgcn[tx]; sbo[tx] = bout[tx]; }
    __syncthreads();

    const int r = tx >> 4, o = tx & 15;
    const int gr = blockIdx.x * 8 + r;          // (b,n) flat, 0..4095
    const int b = gr >> 10, n = gr & 1023;

#pragma unroll
    for (int f = 0; f < FF; f++) {
        const int j = n * FF + f;
        const int cidx = j * NCOL + b * DOUTC + o;
        float v = 0.f;
#pragma unroll
        for (int s = 0; s < KSPLIT; s++) v += g_C[s][cidx];
        v += g_corr[j] * g_M[cidx];
        v = g_dinv[j] * v + sbg[o];
        sg[r][f * DOUTC + o] = fmaxf(v, 0.f);
    }
    __syncthreads();

    float s = sbo[o];
#pragma unroll
    for (int k = 0; k < FF * DOUTC; k++) s = fmaf(sg[r][k], sW[k * DOUTC + o], s);
    out[(size_t)gr * DOUTC + o] = s;
}

extern "C" void kernel_launch(void* const* d_in, const int* in_sizes, int n_in,
                              void* d_out, int out_size) {
    // metadata order: x, factor_embeddings, grid_embeddings, supports,
    //                 ln_gamma, ln_beta, W_gcn, b_gcn, W_out, b_out
    const float* x  = (const float*)d_in[0];
    const float* S  = (const float*)d_in[3];
    const float* Wg = (const float*)d_in[6];
    const float* bg = (const float*)d_in[7];
    const float* Wo = (const float*)d_in[8];
    const float* bo = (const float*)d_in[9];
    float* out = (float*)d_out;

    k_degpart<<<dim3(NF / 256, ROWCH), 256>>>(S);
    k_finalize<<<NF / 256, 256>>>(S);
    k_hs<<<(NB * NF * DOUTC) / 256, 256>>>(x, Wg);
    k_gemm<<<dim3(NF / BM, KSPLIT), 256>>>(S);
    k_out<<<(NB * NN) / 8, 128>>>(Wo, bg, bo, out);
}

// round 7
// speedup vs baseline: 1.1058x; 1.1058x over previous
#include <cuda_runtime.h>

// FactorGNN fused pipeline (dead attention branch removed).
//   A = supports, A[j,j] = (diag==0 ? 1 : diag)
//   deg[j] = sum_i A[i,j];  dinv = deg>0 ? rsqrt(deg) : 0
//   M[i,c] = dinv[i] * (x[b,i,:] @ W_gcn)      c = b*16+o  (64 cols)
//   C[j,c] = sum_i supports[i,j] * M[i,c]      (register-streamed GEMM, split-K=7)
//   g      = relu(dinv[j]*(C + corr[j]*M[j,c]) + b_gcn)
//   out    = g.reshape(.,160) @ W_out + b_out

#define NF     10240
#define NB     4
#define NN     1024
#define FF     10
#define DD     16
#define DOUTC  16
#define NCOL   64
#define ROWCH  40
#define KSPLIT 7
#define KCHUNK 1463          // ceil(10240/7); last chunk = 1462

// Scratch (static device globals: allocation-free per harness rules)
__device__ float g_M[(NF + 64) * NCOL];        // hs, padded 64 rows for stage prefetch
__device__ float g_C[KSPLIT][NF * NCOL];       // split-K partials
__device__ float g_degpart[ROWCH * NF];
__device__ float g_dinv[NF];
__device__ float g_corr[NF];

// ---- packed f32x2 helpers (sm_103a FFMA2 path) ----
__device__ __forceinline__ unsigned long long pk2(float lo, float hi) {
    unsigned long long r;
    asm("mov.b64 %0, {%1, %2};" : "=l"(r) : "f"(lo), "f"(hi));
    return r;
}
__device__ __forceinline__ void fma2(unsigned long long& d,
                                     unsigned long long a, unsigned long long b) {
    asm("fma.rn.f32x2 %0, %1, %2, %0;" : "+l"(d) : "l"(a), "l"(b));
}
__device__ __forceinline__ float2 upk2(unsigned long long v) {
    float2 f;
    asm("mov.b64 {%0, %1}, %2;" : "=f"(f.x), "=f"(f.y) : "l"(v));
    return f;
}

// K1: partial column sums of supports (float4 lanes, HBM-bound)
__global__ void k_degpart(const float* __restrict__ S) {
    int j4 = blockIdx.x * 256 + threadIdx.x;       // float4 column group (2560 total)
    int r0 = blockIdx.y * 256;
    const float4* p = (const float4*)S + (size_t)r0 * (NF / 4) + j4;
    float4 s = make_float4(0.f, 0.f, 0.f, 0.f);
#pragma unroll 8
    for (int r = 0; r < 256; r++) {
        float4 v = __ldcs(p + (size_t)r * (NF / 4));
        s.x += v.x; s.y += v.y; s.z += v.z; s.w += v.w;
    }
    ((float4*)g_degpart)[(size_t)blockIdx.y * (NF / 4) + j4] = s;
}

// K2: reduce partials, self-loop fix, produce dinv & corr
__global__ void k_finalize(const float* __restrict__ S) {
    int j = blockIdx.x * 256 + threadIdx.x;
    float s = 0.f;
#pragma unroll
    for (int p = 0; p < ROWCH; p++) s += g_degpart[p * NF + j];
    float diag = S[(size_t)j * NF + j];
    float corr = (diag == 0.f) ? 1.f : 0.f;
    float deg  = s + corr;
    g_dinv[j] = (deg > 0.f) ? rsqrtf(deg) : 0.f;
    g_corr[j] = corr;
}

// K3: M = dinv[i] * (x @ W_gcn), layout g_M[i*64 + b*16 + o]
__global__ void k_hs(const float* __restrict__ x, const float* __restrict__ Wg) {
    __shared__ float sW[DD * DOUTC];
    if (threadIdx.x < DD * DOUTC) sW[threadIdx.x] = Wg[threadIdx.x];
    __syncthreads();
    int g = blockIdx.x * 256 + threadIdx.x;
    int o = g & 15;
    int rest = g >> 4;
    int i = rest % NF;
    int b = rest / NF;
    const float* xr = x + ((size_t)b * NF + i) * DD;
    float h = 0.f;
#pragma unroll
    for (int d = 0; d < DD; d++) h = fmaf(xr[d], sW[d * DOUTC + o], h);
    g_M[i * NCOL + b * DOUTC + o] = g_dinv[i] * h;
}

// K4: C[ks][j,c] = sum_i S[i,j]*M[i,c].
// 256 thr: 64 j-groups (4 j each, LDG.128 from S) x 4 c-groups (16 c each).
// S: register-streamed (__ldcs, depth-2 prefetch). M: smem, double-buffered 32-row stages.
__global__ __launch_bounds__(256, 2) void k_gemm(const float* __restrict__ S) {
    __shared__ alignas(16) float sM[2][32 * NCOL];

    const int tx = threadIdx.x;
    const int cg = tx >> 6;                 // 0..3
    const int jt = tx & 63;                 // 0..63
    const int j  = blockIdx.x * 256 + jt * 4;
    const int c0 = cg * 16;
    const int ks = blockIdx.y;
    const int i0 = ks * KCHUNK;
    const int i1 = min(i0 + KCHUNK, NF);

    unsigned long long acc[4][8];
#pragma unroll
    for (int q = 0; q < 4; q++)
#pragma unroll
        for (int p = 0; p < 8; p++) acc[q][p] = 0ull;

    // S prefetch pointers (row i0, i0+1; then rolling i+2)
    const float4* Sbase = (const float4*)S + (size_t)j / 4;
    float4 s0 = __ldcs(Sbase + (size_t)i0 * (NF / 4));
    float4 s1 = __ldcs(Sbase + (size_t)min(i0 + 1, NF - 1) * (NF / 4));
    const float4* Sp2 = Sbase + (size_t)min(i0 + 2, NF - 1) * (NF / 4);

    // Stage 0 of M into smem buffer 0
    const float4* Mg = (const float4*)g_M;
    {
        float4 a = Mg[(size_t)i0 * (NCOL / 4) + tx];
        float4 b = Mg[(size_t)i0 * (NCOL / 4) + 256 + tx];
        ((float4*)sM[0])[tx] = a;
        ((float4*)sM[0])[tx + 256] = b;
    }
    __syncthreads();

    for (int sb = i0; sb < i1; sb += 32) {
        const int buf = ((sb - i0) >> 5) & 1;
        const bool has_next = (sb + 32 < i1);

        // issue next-stage M loads (held in regs until after compute)
        float4 preA, preB;
        if (has_next) {
            size_t nb4 = (size_t)(sb + 32) * (NCOL / 4);
            preA = Mg[nb4 + tx];
            preB = Mg[nb4 + 256 + tx];
        }

        const int iend = min(sb + 32, i1);
        for (int i = sb; i < iend; ++i) {
            // S depth-2 prefetch of row i+2
            float4 s2 = __ldcs(Sp2);
            Sp2 += (i + 3 < NF) ? (NF / 4) : 0;

            // M row from smem: 16 floats = 8 b64 pairs (broadcast LDS)
            const float* mr = &sM[buf][(i - sb) * NCOL + c0];
            ulonglong2 mA = *(const ulonglong2*)(mr);
            ulonglong2 mB = *(const ulonglong2*)(mr + 4);
            ulonglong2 mC = *(const ulonglong2*)(mr + 8);
            ulonglong2 mD = *(const ulonglong2*)(mr + 12);
            unsigned long long b0 = mA.x, b1 = mA.y, b2 = mB.x, b3 = mB.y;
            unsigned long long b4 = mC.x, b5 = mC.y, b6 = mD.x, b7 = mD.y;

            unsigned long long a;
            a = pk2(s0.x, s0.x);
            fma2(acc[0][0], a, b0); fma2(acc[0][1], a, b1);
            fma2(acc[0][2], a, b2); fma2(acc[0][3], a, b3);
            fma2(acc[0][4], a, b4); fma2(acc[0][5], a, b5);
            fma2(acc[0][6], a, b6); fma2(acc[0][7], a, b7);
            a = pk2(s0.y, s0.y);
            fma2(acc[1][0], a, b0); fma2(acc[1][1], a, b1);
            fma2(acc[1][2], a, b2); fma2(acc[1][3], a, b3);
            fma2(acc[1][4], a, b4); fma2(acc[1][5], a, b5);
            fma2(acc[1][6], a, b6); fma2(acc[1][7], a, b7);
            a = pk2(s0.z, s0.z);
            fma2(acc[2][0], a, b0); fma2(acc[2][1], a, b1);
            fma2(acc[2][2], a, b2); fma2(acc[2][3], a, b3);
            fma2(acc[2][4], a, b4); fma2(acc[2][5], a, b5);
            fma2(acc[2][6], a, b6); fma2(acc[2][7], a, b7);
            a = pk2(s0.w, s0.w);
            fma2(acc[3][0], a, b0); fma2(acc[3][1], a, b1);
            fma2(acc[3][2], a, b2); fma2(acc[3][3], a, b3);
            fma2(acc[3][4], a, b4); fma2(acc[3][5], a, b5);
            fma2(acc[3][6], a, b6); fma2(acc[3][7], a, b7);

            s0 = s1; s1 = s2;
        }

        if (has_next) {
            __syncthreads();                      // everyone done reading buf
            const int nb = buf ^ 1;
            ((float4*)sM[nb])[tx] = preA;
            ((float4*)sM[nb])[tx + 256] = preB;
            __syncthreads();                      // nb ready
        }
    }

    // write partials: rows j..j+3, cols c0..c0+15
#pragma unroll
    for (int q = 0; q < 4; q++) {
        float* Cp = g_C[ks] + (size_t)(j + q) * NCOL + c0;
        float2 v0 = upk2(acc[q][0]), v1 = upk2(acc[q][1]);
        float2 v2 = upk2(acc[q][2]), v3 = upk2(acc[q][3]);
        float2 v4 = upk2(acc[q][4]), v5 = upk2(acc[q][5]);
        float2 v6 = upk2(acc[q][6]), v7 = upk2(acc[q][7]);
        *(float4*)(Cp +  0) = make_float4(v0.x, v0.y, v1.x, v1.y);
        *(float4*)(Cp +  4) = make_float4(v2.x, v2.y, v3.x, v3.y);
        *(float4*)(Cp +  8) = make_float4(v4.x, v4.y, v5.x, v5.y);
        *(float4*)(Cp + 12) = make_float4(v6.x, v6.y, v7.x, v7.y);
    }
}

// K5: epilogue (sum split-K, diag corr, dinv[j], bias, relu) + output GEMM 160x16
__global__ void k_out(const float* __restrict__ Wout, const float* __restrict__ bgcn,
                      const float* __restrict__ bout, float* __restrict__ out) {
    __shared__ float sW[FF * DOUTC * DOUTC];
    __shared__ float sg[8][FF * DOUTC];
    __shared__ float sbg[DOUTC], sbo[DOUTC];
    const int tx = threadIdx.x;
    for (int i = tx; i < FF * DOUTC * DOUTC; i += 128) sW[i] = Wout[i];
    if (tx < DOUTC) { sbg[tx] = bgcn[tx]; sbo[tx] = bout[tx]; }
    __syncthreads();

    const int r = tx >> 4, o = tx & 15;
    const int gr = blockIdx.x * 8 + r;          // (b,n) flat, 0..4095
    const int b = gr >> 10, n = gr & 1023;

#pragma unroll
    for (int f = 0; f < FF; f++) {
        const int j = n * FF + f;
        const int cidx = j * NCOL + b * DOUTC + o;
        float v = 0.f;
#pragma unroll
        for (int s = 0; s < KSPLIT; s++) v += g_C[s][cidx];
        v += g_corr[j] * g_M[cidx];
        v = g_dinv[j] * v + sbg[o];
        sg[r][f * DOUTC + o] = fmaxf(v, 0.f);
    }
    __syncthreads();

    float s = sbo[o];
#pragma unroll
    for (int k = 0; k < FF * DOUTC; k++) s = fmaf(sg[r][k], sW[k * DOUTC + o], s);
    out[(size_t)gr * DOUTC + o] = s;
}

extern "C" void kernel_launch(void* const* d_in, const int* in_sizes, int n_in,
                              void* d_out, int out_size) {
    // metadata order: x, factor_embeddings, grid_embeddings, supports,
    //                 ln_gamma, ln_beta, W_gcn, b_gcn, W_out, b_out
    const float* x  = (const float*)d_in[0];
    const float* S  = (const float*)d_in[3];
    const float* Wg = (const float*)d_in[6];
    const float* bg = (const float*)d_in[7];
    const float* Wo = (const float*)d_in[8];
    const float* bo = (const float*)d_in[9];
    float* out = (float*)d_out;

    k_degpart<<<dim3(NF / 1024, ROWCH), 256>>>(S);
    k_finalize<<<NF / 256, 256>>>(S);
    k_hs<<<(NB * NF * DOUTC) / 256, 256>>>(x, Wg);
    k_gemm<<<dim3(NF / 256, KSPLIT), 256>>>(S);
    k_out<<<(NB * NN) / 8, 128>>>(Wo, bg, bo, out);
}